// round 16
// baseline (speedup 1.0000x reference)
#include <cuda_runtime.h>
#include <cstdint>

// out[n, :] = weight[idx_n, :] where one_hot[n, idx_n] == 1.0
// N = 8192, VOCAB = 8192, D = 1024, fp32.
//
// Two-phase split:
//   Phase 1 (scan): warp-per-row early-exit scan of one_hot (2KB rounds,
//       streaming loads). Finder lane writes idx[row]. ~5.9 TB/s, near floor.
//   Phase 2 (gather): 8 rows per block, 8 INDEPENDENT float4 loads per
//       thread (MLP=8), idx values staged in smem. 1024 blocks -> all loads
//       in flight almost immediately; streaming stores.

#define N_ROWS  8192
#define VOCAB   8192
#define DIM     1024
#define WARPS_PER_BLOCK 8
#define THREADS (WARPS_PER_BLOCK * 32)
#define GRID    (N_ROWS / WARPS_PER_BLOCK)    // 1024

#define G_ROWS_PER_BLOCK 8
#define G_GRID (N_ROWS / G_ROWS_PER_BLOCK)    // 1024

__device__ int g_idx[N_ROWS];

// ---------------- Phase 1: find the one-hot position per row ----------------
__global__ __launch_bounds__(THREADS) void scan_kernel(
    const float* __restrict__ one_hot)
{
    const int warp_global = (blockIdx.x * blockDim.x + threadIdx.x) >> 5;
    const int lane = threadIdx.x & 31;
    const unsigned FULL = 0xFFFFFFFFu;

    const uint4* __restrict__ row =
        reinterpret_cast<const uint4*>(one_hot + (size_t)warp_global * VOCAB);

    // 4x uint4 per lane = 2KB per round, 16 rounds max.
    #pragma unroll 1
    for (int base = 0; base < VOCAB / 4; base += 128) {
        uint4 v0 = __ldcs(row + base       + lane);
        uint4 v1 = __ldcs(row + base + 32  + lane);
        uint4 v2 = __ldcs(row + base + 64  + lane);
        uint4 v3 = __ldcs(row + base + 96  + lane);

        unsigned nz0 = (v0.x | v0.y | v0.z | v0.w);
        unsigned nz1 = (v1.x | v1.y | v1.z | v1.w);
        unsigned nz2 = (v2.x | v2.y | v2.z | v2.w);
        unsigned nz3 = (v3.x | v3.y | v3.z | v3.w);

        if (__ballot_sync(FULL, (nz0 | nz1 | nz2 | nz3) != 0u)) {
            // exactly one lane holds the hot element; only it writes
            uint4 v; int chunk;
            if      (nz0) { v = v0; chunk = 0; }
            else if (nz1) { v = v1; chunk = 1; }
            else if (nz2) { v = v2; chunk = 2; }
            else          { v = v3; chunk = 3; }
            if (nz0 | nz1 | nz2 | nz3) {
                int e = (v.x != 0u) ? 0 : (v.y != 0u) ? 1 : (v.z != 0u) ? 2 : 3;
                g_idx[warp_global] = (base + chunk * 32 + lane) * 4 + e;
            }
            break;
        }
    }
}

// ---------------- Phase 2: gather weight rows into out ----------------
// 8 rows per block; each thread holds element t of all 8 rows.
// All 8 weight loads are independent -> issued back-to-back (MLP=8).
__global__ __launch_bounds__(256) void gather_kernel(
    const float* __restrict__ weight,
    float* __restrict__ out)
{
    __shared__ int sidx[G_ROWS_PER_BLOCK];
    const int t = threadIdx.x;
    const int row0 = blockIdx.x * G_ROWS_PER_BLOCK;

    if (t < G_ROWS_PER_BLOCK)
        sidx[t] = g_idx[row0 + t];
    __syncthreads();

    const float4* __restrict__ w4 = reinterpret_cast<const float4*>(weight);

    float4 v[G_ROWS_PER_BLOCK];
    #pragma unroll
    for (int r = 0; r < G_ROWS_PER_BLOCK; r++)
        v[r] = w4[(size_t)sidx[r] * (DIM / 4) + t];

    float4* __restrict__ o4 = reinterpret_cast<float4*>(out);
    #pragma unroll
    for (int r = 0; r < G_ROWS_PER_BLOCK; r++)
        __stcs(o4 + (size_t)(row0 + r) * (DIM / 4) + t, v[r]);
}

extern "C" void kernel_launch(void* const* d_in, const int* in_sizes, int n_in,
                              void* d_out, int out_size)
{
    const float* one_hot = (const float*)d_in[0];  // [N, VOCAB] fp32
    const float* weight  = (const float*)d_in[1];  // [VOCAB, D] fp32
    float* out = (float*)d_out;                    // [N, D] fp32

    scan_kernel<<<GRID, THREADS>>>(one_hot);
    gather_kernel<<<G_GRID, 256>>>(weight, out);
}

// round 17
// speedup vs baseline: 1.0334x; 1.0334x over previous
#include <cuda_runtime.h>
#include <cstdint>

// out[n, :] = weight[idx_n, :] where one_hot[n, idx_n] == 1.0
// N = 8192, VOCAB = 8192, D = 1024, fp32.
//
// Overlapped producer/consumer in one fully-resident wave:
//   - 1024 blocks x 256 threads, __launch_bounds__(256,7) (<=36 regs) so ALL
//     blocks are co-resident (262K threads < 148 SMs * 2048) -> spin-safe.
//   - Each block scans its own 8 rows (warp-per-row early-exit, the proven
//     5.9 TB/s code), writing idx+1 into g_idx.
//   - Then it gathers the 8 rows of the block offset by +512, spin-waiting
//     (nanosleep backoff) until that row's idx is published. Early-finishing
//     blocks gather while others still scan -> the gather's ~21MB of random
//     reads hide under the scan stream instead of forming an 11us tail.
//   - A tiny zero kernel resets g_idx each replay (sentinel = 0).

#define N_ROWS  8192
#define VOCAB   8192
#define DIM     1024
#define WARPS_PER_BLOCK 8
#define THREADS (WARPS_PER_BLOCK * 32)
#define GRID    (N_ROWS / WARPS_PER_BLOCK)    // 1024
#define GATHER_OFFSET 512                     // blocks gather rows of b+512

__device__ int g_idx[N_ROWS];                 // 0 = not found yet, else idx+1

__global__ void zero_flags_kernel() {
    int i = blockIdx.x * blockDim.x + threadIdx.x;
    if (i < N_ROWS) g_idx[i] = 0;
}

__global__ __launch_bounds__(THREADS, 7) void scan_gather_kernel(
    const float* __restrict__ one_hot,
    const float* __restrict__ weight,
    float* __restrict__ out)
{
    const int warp_in_block = threadIdx.x >> 5;
    const int lane = threadIdx.x & 31;
    const unsigned FULL = 0xFFFFFFFFu;

    // ---------------- Phase A: scan own row (warp-per-row) ----------------
    {
        const int my_row = blockIdx.x * WARPS_PER_BLOCK + warp_in_block;
        const uint4* __restrict__ row =
            reinterpret_cast<const uint4*>(one_hot + (size_t)my_row * VOCAB);

        // 4x uint4 per lane = 2KB per round, 16 rounds max.
        #pragma unroll 1
        for (int base = 0; base < VOCAB / 4; base += 128) {
            uint4 v0 = __ldcs(row + base       + lane);
            uint4 v1 = __ldcs(row + base + 32  + lane);
            uint4 v2 = __ldcs(row + base + 64  + lane);
            uint4 v3 = __ldcs(row + base + 96  + lane);

            unsigned nz0 = (v0.x | v0.y | v0.z | v0.w);
            unsigned nz1 = (v1.x | v1.y | v1.z | v1.w);
            unsigned nz2 = (v2.x | v2.y | v2.z | v2.w);
            unsigned nz3 = (v3.x | v3.y | v3.z | v3.w);

            if (__ballot_sync(FULL, (nz0 | nz1 | nz2 | nz3) != 0u)) {
                uint4 v; int chunk;
                if      (nz0) { v = v0; chunk = 0; }
                else if (nz1) { v = v1; chunk = 1; }
                else if (nz2) { v = v2; chunk = 2; }
                else          { v = v3; chunk = 3; }
                if (nz0 | nz1 | nz2 | nz3) {
                    int e = (v.x != 0u) ? 0 : (v.y != 0u) ? 1 : (v.z != 0u) ? 2 : 3;
                    // publish idx+1 (0 is the "not ready" sentinel)
                    *(volatile int*)&g_idx[my_row] =
                        (base + chunk * 32 + lane) * 4 + e + 1;
                }
                break;
            }
        }
    }

    // ------------- Phase B: gather rows of block (b + 512) % 1024 ----------
    {
        const int gb = (blockIdx.x + GATHER_OFFSET) & (GRID - 1);
        const int g_row = gb * WARPS_PER_BLOCK + warp_in_block;

        // spin until that row's scanner (co-resident block) publishes
        int idxp;
        if (lane == 0) {
            idxp = *(volatile int*)&g_idx[g_row];
            while (idxp == 0) {
                __nanosleep(64);
                idxp = *(volatile int*)&g_idx[g_row];
            }
        }
        idxp = __shfl_sync(FULL, idxp, 0);
        const int idx = idxp - 1;

        const float4* __restrict__ wrow =
            reinterpret_cast<const float4*>(weight + (size_t)idx * DIM);
        float4* __restrict__ orow =
            reinterpret_cast<float4*>(out + (size_t)g_row * DIM);

        #pragma unroll
        for (int i = 0; i < DIM / 4 / 32; i++)   // 8 iterations, 4KB
            __stcs(orow + i * 32 + lane, wrow[i * 32 + lane]);
    }
}

extern "C" void kernel_launch(void* const* d_in, const int* in_sizes, int n_in,
                              void* d_out, int out_size)
{
    const float* one_hot = (const float*)d_in[0];  // [N, VOCAB] fp32
    const float* weight  = (const float*)d_in[1];  // [VOCAB, D] fp32
    float* out = (float*)d_out;                    // [N, D] fp32

    zero_flags_kernel<<<N_ROWS / 256, 256>>>();
    scan_gather_kernel<<<GRID, THREADS>>>(one_hot, weight, out);
}